// round 1
// baseline (speedup 1.0000x reference)
#include <cuda_runtime.h>
#include <math.h>

// Problem constants
#define BATCH 2
#define SEQ   2048
#define DIM   1024
#define HEADS 16
#define HDIM  64
#define TOK   (BATCH*SEQ)          // 4096
#define INNER 4096

// ---------------- scratch buffers (no allocations allowed) ----------------
__device__ float g_hx [TOK*DIM];        // 16 MB  LN1 output
__device__ float g_qkv[TOK*3*DIM];      // 48 MB  QKV (rope applied in-place)
__device__ float g_att[TOK*DIM];        // 16 MB  attention output (merged heads)
__device__ float g_x1 [TOK*DIM];        // 16 MB  x + attn@Wproj
__device__ float g_h2 [TOK*DIM];        // 16 MB  LN2 output
__device__ float g_ff [TOK*INNER];      // 64 MB  gelu(h2@W1)

// ---------------- LayerNorm: one block per row, D=1024 ----------------
__global__ void __launch_bounds__(256) ln_kernel(const float* __restrict__ in,
                                                 const float* __restrict__ w,
                                                 const float* __restrict__ b,
                                                 float* __restrict__ out) {
    int row = blockIdx.x;
    int tid = threadIdx.x;                      // 256 threads, 4 elems each
    const float4* xr = (const float4*)(in + (size_t)row * DIM);
    float4 v = xr[tid];
    float s1 = v.x + v.y + v.z + v.w;
    float s2 = v.x*v.x + v.y*v.y + v.z*v.z + v.w*v.w;
    #pragma unroll
    for (int o = 16; o; o >>= 1) {
        s1 += __shfl_xor_sync(0xffffffffu, s1, o);
        s2 += __shfl_xor_sync(0xffffffffu, s2, o);
    }
    __shared__ float r1[8], r2[8];
    if ((tid & 31) == 0) { r1[tid >> 5] = s1; r2[tid >> 5] = s2; }
    __syncthreads();
    if (tid < 32) {
        float a  = (tid < 8) ? r1[tid] : 0.f;
        float b2 = (tid < 8) ? r2[tid] : 0.f;
        #pragma unroll
        for (int o = 4; o; o >>= 1) {
            a  += __shfl_xor_sync(0xffffffffu, a,  o);
            b2 += __shfl_xor_sync(0xffffffffu, b2, o);
        }
        if (tid == 0) { r1[0] = a; r2[0] = b2; }
    }
    __syncthreads();
    float mean = r1[0] * (1.f / DIM);
    float var  = r2[0] * (1.f / DIM) - mean * mean;
    float inv  = rsqrtf(var + 1e-5f);
    float4 wv = ((const float4*)w)[tid];
    float4 bv = ((const float4*)b)[tid];
    float4 o4;
    o4.x = (v.x - mean) * inv * wv.x + bv.x;
    o4.y = (v.y - mean) * inv * wv.y + bv.y;
    o4.z = (v.z - mean) * inv * wv.z + bv.z;
    o4.w = (v.w - mean) * inv * wv.w + bv.w;
    ((float4*)(out + (size_t)row * DIM))[tid] = o4;
}

// ---------------- RoPE on q,k in-place (qkv layout: row=token, col=g*1024+h*64+d) ----
__global__ void __launch_bounds__(512) rope_kernel(float* __restrict__ qkv,
                                                   const float* __restrict__ sinp,
                                                   const float* __restrict__ cosp) {
    int token = blockIdx.x;
    int s = token & (SEQ - 1);
    int tid = threadIdx.x;        // 512 = 16 heads * 32 pair-dims
    int h = tid >> 5;
    int d = tid & 31;
    float c1 = cosp[s * HDIM + d];
    float s1 = sinp[s * HDIM + d];
    float c2 = cosp[s * HDIM + d + 32];
    float s2 = sinp[s * HDIM + d + 32];
    #pragma unroll
    for (int g = 0; g < 2; g++) {               // q then k
        float* p = qkv + (size_t)token * (3 * DIM) + g * DIM + h * HDIM + d;
        float x1 = p[0], x2 = p[32];
        p[0]  = x1 * c1 - x2 * s1;
        p[32] = x2 * c2 + x1 * s2;
    }
}

// ---------------- SGEMM 128x128, BK=8, 256 threads, 8x8/thread ----------------
// EPI: 0 = plain, 1 = exact GELU, 2 = add residual R
__device__ __forceinline__ float gelu_exact(float x) {
    return 0.5f * x * (1.f + erff(x * 0.70710678118654752f));
}

template<int EPI>
__global__ void __launch_bounds__(256) sgemm_kernel(const float* __restrict__ A,
                                                    const float* __restrict__ B,
                                                    const float* __restrict__ R,
                                                    float* __restrict__ C,
                                                    int M, int N, int K) {
    __shared__ float As[8][128];
    __shared__ float Bs[8][128];
    int tid  = threadIdx.x;
    int row0 = blockIdx.y * 128;
    int col0 = blockIdx.x * 128;
    int aRow = tid >> 1;            // 0..127
    int aCol = (tid & 1) * 4;       // 0 or 4
    int bRow = tid >> 5;            // 0..7
    int bCol = (tid & 31) * 4;      // 0..124
    const float* Ap = A + (size_t)(row0 + aRow) * K + aCol;
    const float* Bp = B + (size_t)bRow * N + col0 + bCol;
    int tr = (tid >> 4) * 8;
    int tc = (tid & 15) * 8;
    float acc[8][8];
    #pragma unroll
    for (int i = 0; i < 8; i++)
        #pragma unroll
        for (int j = 0; j < 8; j++) acc[i][j] = 0.f;

    for (int k0 = 0; k0 < K; k0 += 8) {
        float4 av = *(const float4*)Ap;
        float4 bv = *(const float4*)Bp;
        As[aCol + 0][aRow] = av.x;
        As[aCol + 1][aRow] = av.y;
        As[aCol + 2][aRow] = av.z;
        As[aCol + 3][aRow] = av.w;
        *(float4*)&Bs[bRow][bCol] = bv;
        __syncthreads();
        #pragma unroll
        for (int kk = 0; kk < 8; kk++) {
            float4 a0 = *(const float4*)&As[kk][tr];
            float4 a1 = *(const float4*)&As[kk][tr + 4];
            float4 b0 = *(const float4*)&Bs[kk][tc];
            float4 b1 = *(const float4*)&Bs[kk][tc + 4];
            float a[8] = {a0.x, a0.y, a0.z, a0.w, a1.x, a1.y, a1.z, a1.w};
            float b[8] = {b0.x, b0.y, b0.z, b0.w, b1.x, b1.y, b1.z, b1.w};
            #pragma unroll
            for (int i = 0; i < 8; i++)
                #pragma unroll
                for (int j = 0; j < 8; j++)
                    acc[i][j] = fmaf(a[i], b[j], acc[i][j]);
        }
        __syncthreads();
        Ap += 8;
        Bp += (size_t)8 * N;
    }
    #pragma unroll
    for (int i = 0; i < 8; i++) {
        size_t base = (size_t)(row0 + tr + i) * N + col0 + tc;
        #pragma unroll
        for (int j = 0; j < 8; j++) {
            float v = acc[i][j];
            if (EPI == 1) v = gelu_exact(v);
            if (EPI == 2) v += R[base + j];
            C[base + j] = v;
        }
    }
}

// ---------------- Flash attention (causal), fp32 ----------------
// grid: (SEQ/64, BATCH*HEADS); block 256 (16x16)
// Q tile 64 rows, K/V chunks of 32 rows, online softmax.
__global__ void __launch_bounds__(256) flash_kernel(const float* __restrict__ qkv,
                                                    float* __restrict__ out) {
    __shared__ float Qs[64][65];
    __shared__ float Ks[32][65];
    __shared__ float Vs[32][65];
    __shared__ float Ps[64][33];
    int tid = threadIdx.x;
    int qt = blockIdx.x;
    int q0 = qt * 64;
    int bh = blockIdx.y;
    int b  = bh >> 4;
    int h  = bh & 15;
    const float* base = qkv + (size_t)b * SEQ * (3 * DIM);

    for (int idx = tid; idx < 64 * 64; idx += 256) {
        int r = idx >> 6, d = idx & 63;
        Qs[r][d] = base[(size_t)(q0 + r) * (3 * DIM) + h * HDIM + d];
    }

    int ty = tid >> 4, tx = tid & 15;
    float m[4], l[4], acc[4][4];
    #pragma unroll
    for (int i = 0; i < 4; i++) {
        m[i] = -INFINITY; l[i] = 0.f;
        #pragma unroll
        for (int j = 0; j < 4; j++) acc[i][j] = 0.f;
    }

    int nk = 2 * qt + 2;   // number of 32-row k-chunks covering [0, q0+64)
    for (int kt = 0; kt < nk; kt++) {
        int k0 = kt * 32;
        __syncthreads();   // prev PV reads done (also covers Q-load on iter 0)
        for (int idx = tid; idx < 32 * 64; idx += 256) {
            int r = idx >> 6, d = idx & 63;
            size_t rowoff = (size_t)(k0 + r) * (3 * DIM) + h * HDIM + d;
            Ks[r][d] = base[rowoff + DIM];
            Vs[r][d] = base[rowoff + 2 * DIM];
        }
        __syncthreads();

        // scores: 4 rows x 2 cols per thread
        float s[4][2];
        #pragma unroll
        for (int i = 0; i < 4; i++) { s[i][0] = 0.f; s[i][1] = 0.f; }
        #pragma unroll 8
        for (int kk = 0; kk < 64; kk++) {
            float a0 = Qs[4 * ty + 0][kk];
            float a1 = Qs[4 * ty + 1][kk];
            float a2 = Qs[4 * ty + 2][kk];
            float a3 = Qs[4 * ty + 3][kk];
            float c0 = Ks[2 * tx + 0][kk];
            float c1 = Ks[2 * tx + 1][kk];
            s[0][0] = fmaf(a0, c0, s[0][0]); s[0][1] = fmaf(a0, c1, s[0][1]);
            s[1][0] = fmaf(a1, c0, s[1][0]); s[1][1] = fmaf(a1, c1, s[1][1]);
            s[2][0] = fmaf(a2, c0, s[2][0]); s[2][1] = fmaf(a2, c1, s[2][1]);
            s[3][0] = fmaf(a3, c0, s[3][0]); s[3][1] = fmaf(a3, c1, s[3][1]);
        }
        #pragma unroll
        for (int i = 0; i < 4; i++) {
            int rg = q0 + 4 * ty + i;
            float s0 = s[i][0] * 0.125f;
            float s1 = s[i][1] * 0.125f;
            if (k0 + 2 * tx + 0 > rg) s0 = -INFINITY;
            if (k0 + 2 * tx + 1 > rg) s1 = -INFINITY;
            float mr = fmaxf(s0, s1);
            #pragma unroll
            for (int o = 1; o < 16; o <<= 1)
                mr = fmaxf(mr, __shfl_xor_sync(0xffffffffu, mr, o));
            float mn = fmaxf(m[i], mr);
            float alpha = __expf(m[i] - mn);
            m[i] = mn;
            float p0 = __expf(s0 - mn);
            float p1 = __expf(s1 - mn);
            Ps[4 * ty + i][2 * tx + 0] = p0;
            Ps[4 * ty + i][2 * tx + 1] = p1;
            float rs = p0 + p1;
            #pragma unroll
            for (int o = 1; o < 16; o <<= 1)
                rs += __shfl_xor_sync(0xffffffffu, rs, o);
            l[i] = l[i] * alpha + rs;
            #pragma unroll
            for (int j = 0; j < 4; j++) acc[i][j] *= alpha;
        }
        __syncthreads();   // Ps complete before PV
        #pragma unroll 4
        for (int kk = 0; kk < 32; kk++) {
            float p0 = Ps[4 * ty + 0][kk];
            float p1 = Ps[4 * ty + 1][kk];
            float p2 = Ps[4 * ty + 2][kk];
            float p3 = Ps[4 * ty + 3][kk];
            float v0 = Vs[kk][4 * tx + 0];
            float v1 = Vs[kk][4 * tx + 1];
            float v2 = Vs[kk][4 * tx + 2];
            float v3 = Vs[kk][4 * tx + 3];
            acc[0][0] = fmaf(p0, v0, acc[0][0]); acc[0][1] = fmaf(p0, v1, acc[0][1]);
            acc[0][2] = fmaf(p0, v2, acc[0][2]); acc[0][3] = fmaf(p0, v3, acc[0][3]);
            acc[1][0] = fmaf(p1, v0, acc[1][0]); acc[1][1] = fmaf(p1, v1, acc[1][1]);
            acc[1][2] = fmaf(p1, v2, acc[1][2]); acc[1][3] = fmaf(p1, v3, acc[1][3]);
            acc[2][0] = fmaf(p2, v0, acc[2][0]); acc[2][1] = fmaf(p2, v1, acc[2][1]);
            acc[2][2] = fmaf(p2, v2, acc[2][2]); acc[2][3] = fmaf(p2, v3, acc[2][3]);
            acc[3][0] = fmaf(p3, v0, acc[3][0]); acc[3][1] = fmaf(p3, v1, acc[3][1]);
            acc[3][2] = fmaf(p3, v2, acc[3][2]); acc[3][3] = fmaf(p3, v3, acc[3][3]);
        }
    }
    #pragma unroll
    for (int i = 0; i < 4; i++) {
        float invl = 1.f / l[i];
        size_t rowbase = (size_t)(b * SEQ + q0 + 4 * ty + i) * DIM + h * HDIM + 4 * tx;
        #pragma unroll
        for (int j = 0; j < 4; j++)
            out[rowbase + j] = acc[i][j] * invl;
    }
}

// ---------------- launch ----------------
extern "C" void kernel_launch(void* const* d_in, const int* in_sizes, int n_in,
                              void* d_out, int out_size) {
    const float* x     = (const float*)d_in[0];
    // d_in[1] = mask (implicit causal; unused)
    const float* sinp  = (const float*)d_in[2];
    const float* cosp  = (const float*)d_in[3];
    const float* ln1w  = (const float*)d_in[4];
    const float* ln1b  = (const float*)d_in[5];
    const float* wqkv  = (const float*)d_in[6];
    const float* wproj = (const float*)d_in[7];
    const float* ln2w  = (const float*)d_in[8];
    const float* ln2b  = (const float*)d_in[9];
    const float* wfc1  = (const float*)d_in[10];
    const float* wfc2  = (const float*)d_in[11];
    float* out = (float*)d_out;

    static float *hx = nullptr, *qkvb, *attb, *x1b, *h2b, *ffb;
    if (!hx) {  // resolved on the (uncaptured) correctness call; capture call is launches only
        cudaGetSymbolAddress((void**)&hx,   g_hx);
        cudaGetSymbolAddress((void**)&qkvb, g_qkv);
        cudaGetSymbolAddress((void**)&attb, g_att);
        cudaGetSymbolAddress((void**)&x1b,  g_x1);
        cudaGetSymbolAddress((void**)&h2b,  g_h2);
        cudaGetSymbolAddress((void**)&ffb,  g_ff);
    }

    // 1. LN1
    ln_kernel<<<TOK, 256>>>(x, ln1w, ln1b, hx);
    // 2. QKV GEMM: [4096,1024]@[1024,3072]
    sgemm_kernel<0><<<dim3(3072 / 128, TOK / 128), 256>>>(hx, wqkv, nullptr, qkvb, TOK, 3 * DIM, DIM);
    // 3. RoPE on q,k in place
    rope_kernel<<<TOK, 512>>>(qkvb, sinp, cosp);
    // 4. causal flash attention -> merged-head output
    flash_kernel<<<dim3(SEQ / 64, BATCH * HEADS), 256>>>(qkvb, attb);
    // 5. proj GEMM + residual: x1 = x + att@Wproj
    sgemm_kernel<2><<<dim3(DIM / 128, TOK / 128), 256>>>(attb, wproj, x, x1b, TOK, DIM, DIM);
    // 6. LN2
    ln_kernel<<<TOK, 256>>>(x1b, ln2w, ln2b, h2b);
    // 7. FC1 + exact GELU
    sgemm_kernel<1><<<dim3(INNER / 128, TOK / 128), 256>>>(h2b, wfc1, nullptr, ffb, TOK, INNER, DIM);
    // 8. FC2 + residual -> final output
    sgemm_kernel<2><<<dim3(DIM / 128, TOK / 128), 256>>>(ffb, wfc2, x1b, out, TOK, DIM, INNER);
}

// round 2
// speedup vs baseline: 1.0008x; 1.0008x over previous
#include <cuda_runtime.h>
#include <math.h>

// Problem constants
#define BATCH 2
#define SEQ   2048
#define DIM   1024
#define HEADS 16
#define HDIM  64
#define TOK   (BATCH*SEQ)          // 4096
#define INNER 4096

// ---------------- scratch buffers (no allocations allowed) ----------------
__device__ float g_hx [TOK*DIM];        // 16 MB  LN1 output
__device__ float g_qkv[TOK*3*DIM];      // 48 MB  QKV (rope applied in-place)
__device__ float g_att[TOK*DIM];        // 16 MB  attention output (merged heads)
__device__ float g_x1 [TOK*DIM];        // 16 MB  x + attn@Wproj
__device__ float g_h2 [TOK*DIM];        // 16 MB  LN2 output
__device__ float g_ff [TOK*INNER];      // 64 MB  gelu(h2@W1)

// ---------------- LayerNorm: one block per row, D=1024 ----------------
__global__ void __launch_bounds__(256) ln_kernel(const float* __restrict__ in,
                                                 const float* __restrict__ w,
                                                 const float* __restrict__ b,
                                                 float* __restrict__ out) {
    int row = blockIdx.x;
    int tid = threadIdx.x;                      // 256 threads, 4 elems each
    const float4* xr = (const float4*)(in + (size_t)row * DIM);
    float4 v = xr[tid];
    float s1 = v.x + v.y + v.z + v.w;
    float s2 = v.x*v.x + v.y*v.y + v.z*v.z + v.w*v.w;
    #pragma unroll
    for (int o = 16; o; o >>= 1) {
        s1 += __shfl_xor_sync(0xffffffffu, s1, o);
        s2 += __shfl_xor_sync(0xffffffffu, s2, o);
    }
    __shared__ float r1[8], r2[8];
    if ((tid & 31) == 0) { r1[tid >> 5] = s1; r2[tid >> 5] = s2; }
    __syncthreads();
    if (tid < 32) {
        float a  = (tid < 8) ? r1[tid] : 0.f;
        float b2 = (tid < 8) ? r2[tid] : 0.f;
        #pragma unroll
        for (int o = 4; o; o >>= 1) {
            a  += __shfl_xor_sync(0xffffffffu, a,  o);
            b2 += __shfl_xor_sync(0xffffffffu, b2, o);
        }
        if (tid == 0) { r1[0] = a; r2[0] = b2; }
    }
    __syncthreads();
    float mean = r1[0] * (1.f / DIM);
    float var  = r2[0] * (1.f / DIM) - mean * mean;
    float inv  = rsqrtf(var + 1e-5f);
    float4 wv = ((const float4*)w)[tid];
    float4 bv = ((const float4*)b)[tid];
    float4 o4;
    o4.x = (v.x - mean) * inv * wv.x + bv.x;
    o4.y = (v.y - mean) * inv * wv.y + bv.y;
    o4.z = (v.z - mean) * inv * wv.z + bv.z;
    o4.w = (v.w - mean) * inv * wv.w + bv.w;
    ((float4*)(out + (size_t)row * DIM))[tid] = o4;
}

// ---------------- RoPE on q,k in-place (qkv layout: row=token, col=g*1024+h*64+d) ----
__global__ void __launch_bounds__(512) rope_kernel(float* __restrict__ qkv,
                                                   const float* __restrict__ sinp,
                                                   const float* __restrict__ cosp) {
    int token = blockIdx.x;
    int s = token & (SEQ - 1);
    int tid = threadIdx.x;        // 512 = 16 heads * 32 pair-dims
    int h = tid >> 5;
    int d = tid & 31;
    float c1 = cosp[s * HDIM + d];
    float s1 = sinp[s * HDIM + d];
    float c2 = cosp[s * HDIM + d + 32];
    float s2 = sinp[s * HDIM + d + 32];
    #pragma unroll
    for (int g = 0; g < 2; g++) {               // q then k
        float* p = qkv + (size_t)token * (3 * DIM) + g * DIM + h * HDIM + d;
        float x1 = p[0], x2 = p[32];
        p[0]  = x1 * c1 - x2 * s1;
        p[32] = x2 * c2 + x1 * s2;
    }
}

// ---------------- SGEMM 128x128, BK=8, 256 threads, 8x8/thread ----------------
// EPI: 0 = plain, 1 = exact GELU, 2 = add residual R
__device__ __forceinline__ float gelu_exact(float x) {
    return 0.5f * x * (1.f + erff(x * 0.70710678118654752f));
}

template<int EPI>
__global__ void __launch_bounds__(256) sgemm_kernel(const float* __restrict__ A,
                                                    const float* __restrict__ B,
                                                    const float* __restrict__ R,
                                                    float* __restrict__ C,
                                                    int M, int N, int K) {
    __shared__ float As[8][128];
    __shared__ float Bs[8][128];
    int tid  = threadIdx.x;
    int row0 = blockIdx.y * 128;
    int col0 = blockIdx.x * 128;
    int aRow = tid >> 1;            // 0..127
    int aCol = (tid & 1) * 4;       // 0 or 4
    int bRow = tid >> 5;            // 0..7
    int bCol = (tid & 31) * 4;      // 0..124
    const float* Ap = A + (size_t)(row0 + aRow) * K + aCol;
    const float* Bp = B + (size_t)bRow * N + col0 + bCol;
    int tr = (tid >> 4) * 8;
    int tc = (tid & 15) * 8;
    float acc[8][8];
    #pragma unroll
    for (int i = 0; i < 8; i++)
        #pragma unroll
        for (int j = 0; j < 8; j++) acc[i][j] = 0.f;

    for (int k0 = 0; k0 < K; k0 += 8) {
        float4 av = *(const float4*)Ap;
        float4 bv = *(const float4*)Bp;
        As[aCol + 0][aRow] = av.x;
        As[aCol + 1][aRow] = av.y;
        As[aCol + 2][aRow] = av.z;
        As[aCol + 3][aRow] = av.w;
        *(float4*)&Bs[bRow][bCol] = bv;
        __syncthreads();
        #pragma unroll
        for (int kk = 0; kk < 8; kk++) {
            float4 a0 = *(const float4*)&As[kk][tr];
            float4 a1 = *(const float4*)&As[kk][tr + 4];
            float4 b0 = *(const float4*)&Bs[kk][tc];
            float4 b1 = *(const float4*)&Bs[kk][tc + 4];
            float a[8] = {a0.x, a0.y, a0.z, a0.w, a1.x, a1.y, a1.z, a1.w};
            float b[8] = {b0.x, b0.y, b0.z, b0.w, b1.x, b1.y, b1.z, b1.w};
            #pragma unroll
            for (int i = 0; i < 8; i++)
                #pragma unroll
                for (int j = 0; j < 8; j++)
                    acc[i][j] = fmaf(a[i], b[j], acc[i][j]);
        }
        __syncthreads();
        Ap += 8;
        Bp += (size_t)8 * N;
    }
    #pragma unroll
    for (int i = 0; i < 8; i++) {
        size_t base = (size_t)(row0 + tr + i) * N + col0 + tc;
        #pragma unroll
        for (int j = 0; j < 8; j++) {
            float v = acc[i][j];
            if (EPI == 1) v = gelu_exact(v);
            if (EPI == 2) v += R[base + j];
            C[base + j] = v;
        }
    }
}

// ---------------- Flash attention (causal), fp32 ----------------
// grid: (SEQ/64, BATCH*HEADS); block 256 (16x16)
// Q tile 64 rows, K/V chunks of 32 rows, online softmax.
__global__ void __launch_bounds__(256) flash_kernel(const float* __restrict__ qkv,
                                                    float* __restrict__ out) {
    __shared__ float Qs[64][65];
    __shared__ float Ks[32][65];
    __shared__ float Vs[32][65];
    __shared__ float Ps[64][33];
    int tid = threadIdx.x;
    int qt = blockIdx.x;
    int q0 = qt * 64;
    int bh = blockIdx.y;
    int b  = bh >> 4;
    int h  = bh & 15;
    const float* base = qkv + (size_t)b * SEQ * (3 * DIM);

    for (int idx = tid; idx < 64 * 64; idx += 256) {
        int r = idx >> 6, d = idx & 63;
        Qs[r][d] = base[(size_t)(q0 + r) * (3 * DIM) + h * HDIM + d];
    }

    int ty = tid >> 4, tx = tid & 15;
    float m[4], l[4], acc[4][4];
    #pragma unroll
    for (int i = 0; i < 4; i++) {
        m[i] = -INFINITY; l[i] = 0.f;
        #pragma unroll
        for (int j = 0; j < 4; j++) acc[i][j] = 0.f;
    }

    int nk = 2 * qt + 2;   // number of 32-row k-chunks covering [0, q0+64)
    for (int kt = 0; kt < nk; kt++) {
        int k0 = kt * 32;
        __syncthreads();   // prev PV reads done (also covers Q-load on iter 0)
        for (int idx = tid; idx < 32 * 64; idx += 256) {
            int r = idx >> 6, d = idx & 63;
            size_t rowoff = (size_t)(k0 + r) * (3 * DIM) + h * HDIM + d;
            Ks[r][d] = base[rowoff + DIM];
            Vs[r][d] = base[rowoff + 2 * DIM];
        }
        __syncthreads();

        // scores: 4 rows x 2 cols per thread
        float s[4][2];
        #pragma unroll
        for (int i = 0; i < 4; i++) { s[i][0] = 0.f; s[i][1] = 0.f; }
        #pragma unroll 8
        for (int kk = 0; kk < 64; kk++) {
            float a0 = Qs[4 * ty + 0][kk];
            float a1 = Qs[4 * ty + 1][kk];
            float a2 = Qs[4 * ty + 2][kk];
            float a3 = Qs[4 * ty + 3][kk];
            float c0 = Ks[2 * tx + 0][kk];
            float c1 = Ks[2 * tx + 1][kk];
            s[0][0] = fmaf(a0, c0, s[0][0]); s[0][1] = fmaf(a0, c1, s[0][1]);
            s[1][0] = fmaf(a1, c0, s[1][0]); s[1][1] = fmaf(a1, c1, s[1][1]);
            s[2][0] = fmaf(a2, c0, s[2][0]); s[2][1] = fmaf(a2, c1, s[2][1]);
            s[3][0] = fmaf(a3, c0, s[3][0]); s[3][1] = fmaf(a3, c1, s[3][1]);
        }
        #pragma unroll
        for (int i = 0; i < 4; i++) {
            int rg = q0 + 4 * ty + i;
            float s0 = s[i][0] * 0.125f;
            float s1 = s[i][1] * 0.125f;
            if (k0 + 2 * tx + 0 > rg) s0 = -INFINITY;
            if (k0 + 2 * tx + 1 > rg) s1 = -INFINITY;
            float mr = fmaxf(s0, s1);
            #pragma unroll
            for (int o = 1; o < 16; o <<= 1)
                mr = fmaxf(mr, __shfl_xor_sync(0xffffffffu, mr, o));
            float mn = fmaxf(m[i], mr);
            float alpha = __expf(m[i] - mn);
            m[i] = mn;
            float p0 = __expf(s0 - mn);
            float p1 = __expf(s1 - mn);
            Ps[4 * ty + i][2 * tx + 0] = p0;
            Ps[4 * ty + i][2 * tx + 1] = p1;
            float rs = p0 + p1;
            #pragma unroll
            for (int o = 1; o < 16; o <<= 1)
                rs += __shfl_xor_sync(0xffffffffu, rs, o);
            l[i] = l[i] * alpha + rs;
            #pragma unroll
            for (int j = 0; j < 4; j++) acc[i][j] *= alpha;
        }
        __syncthreads();   // Ps complete before PV
        #pragma unroll 4
        for (int kk = 0; kk < 32; kk++) {
            float p0 = Ps[4 * ty + 0][kk];
            float p1 = Ps[4 * ty + 1][kk];
            float p2 = Ps[4 * ty + 2][kk];
            float p3 = Ps[4 * ty + 3][kk];
            float v0 = Vs[kk][4 * tx + 0];
            float v1 = Vs[kk][4 * tx + 1];
            float v2 = Vs[kk][4 * tx + 2];
            float v3 = Vs[kk][4 * tx + 3];
            acc[0][0] = fmaf(p0, v0, acc[0][0]); acc[0][1] = fmaf(p0, v1, acc[0][1]);
            acc[0][2] = fmaf(p0, v2, acc[0][2]); acc[0][3] = fmaf(p0, v3, acc[0][3]);
            acc[1][0] = fmaf(p1, v0, acc[1][0]); acc[1][1] = fmaf(p1, v1, acc[1][1]);
            acc[1][2] = fmaf(p1, v2, acc[1][2]); acc[1][3] = fmaf(p1, v3, acc[1][3]);
            acc[2][0] = fmaf(p2, v0, acc[2][0]); acc[2][1] = fmaf(p2, v1, acc[2][1]);
            acc[2][2] = fmaf(p2, v2, acc[2][2]); acc[2][3] = fmaf(p2, v3, acc[2][3]);
            acc[3][0] = fmaf(p3, v0, acc[3][0]); acc[3][1] = fmaf(p3, v1, acc[3][1]);
            acc[3][2] = fmaf(p3, v2, acc[3][2]); acc[3][3] = fmaf(p3, v3, acc[3][3]);
        }
    }
    #pragma unroll
    for (int i = 0; i < 4; i++) {
        float invl = 1.f / l[i];
        size_t rowbase = (size_t)(b * SEQ + q0 + 4 * ty + i) * DIM + h * HDIM + 4 * tx;
        #pragma unroll
        for (int j = 0; j < 4; j++)
            out[rowbase + j] = acc[i][j] * invl;
    }
}

// ---------------- launch ----------------
extern "C" void kernel_launch(void* const* d_in, const int* in_sizes, int n_in,
                              void* d_out, int out_size) {
    const float* x     = (const float*)d_in[0];
    // d_in[1] = mask (implicit causal; unused)
    const float* sinp  = (const float*)d_in[2];
    const float* cosp  = (const float*)d_in[3];
    const float* ln1w  = (const float*)d_in[4];
    const float* ln1b  = (const float*)d_in[5];
    const float* wqkv  = (const float*)d_in[6];
    const float* wproj = (const float*)d_in[7];
    const float* ln2w  = (const float*)d_in[8];
    const float* ln2b  = (const float*)d_in[9];
    const float* wfc1  = (const float*)d_in[10];
    const float* wfc2  = (const float*)d_in[11];
    float* out = (float*)d_out;

    static float *hx = nullptr, *qkvb, *attb, *x1b, *h2b, *ffb;
    if (!hx) {  // resolved on the (uncaptured) correctness call; capture call is launches only
        cudaGetSymbolAddress((void**)&hx,   g_hx);
        cudaGetSymbolAddress((void**)&qkvb, g_qkv);
        cudaGetSymbolAddress((void**)&attb, g_att);
        cudaGetSymbolAddress((void**)&x1b,  g_x1);
        cudaGetSymbolAddress((void**)&h2b,  g_h2);
        cudaGetSymbolAddress((void**)&ffb,  g_ff);
    }

    // 1. LN1
    ln_kernel<<<TOK, 256>>>(x, ln1w, ln1b, hx);
    // 2. QKV GEMM: [4096,1024]@[1024,3072]
    sgemm_kernel<0><<<dim3(3072 / 128, TOK / 128), 256>>>(hx, wqkv, nullptr, qkvb, TOK, 3 * DIM, DIM);
    // 3. RoPE on q,k in place
    rope_kernel<<<TOK, 512>>>(qkvb, sinp, cosp);
    // 4. causal flash attention -> merged-head output
    flash_kernel<<<dim3(SEQ / 64, BATCH * HEADS), 256>>>(qkvb, attb);
    // 5. proj GEMM + residual: x1 = x + att@Wproj
    sgemm_kernel<2><<<dim3(DIM / 128, TOK / 128), 256>>>(attb, wproj, x, x1b, TOK, DIM, DIM);
    // 6. LN2
    ln_kernel<<<TOK, 256>>>(x1b, ln2w, ln2b, h2b);
    // 7. FC1 + exact GELU
    sgemm_kernel<1><<<dim3(INNER / 128, TOK / 128), 256>>>(h2b, wfc1, nullptr, ffb, TOK, INNER, DIM);
    // 8. FC2 + residual -> final output
    sgemm_kernel<2><<<dim3(DIM / 128, TOK / 128), 256>>>(ffb, wfc2, x1b, out, TOK, DIM, INNER);
}